// round 8
// baseline (speedup 1.0000x reference)
#include <cuda_runtime.h>
#include <cuda_bf16.h>
#include <math.h>
#include <stdint.h>

// ---------------------------------------------------------------- constants
#define B_    16
#define T_    1024
#define IN_   1024
#define MEM_  64
#define OUT_  1024
#define C_    32
#define HN_   (2*MEM_ + 2*OUT_)      // 2176
#define NTOK  (B_*T_)                // 16384
#define KMIX  (MEM_*2*C_)            // 4096

// ---------------------------------------------------------------- scratch
__device__ float g_h [(size_t)NTOK * HN_];
__device__ float g_y [(size_t)NTOK * MEM_];
__device__ float g_z [(size_t)NTOK * OUT_];
__device__ __nv_bfloat16 g_xh [(size_t)NTOK * IN_];
__device__ __nv_bfloat16 g_xl [(size_t)NTOK * IN_];
__device__ __nv_bfloat16 g_w1h[(size_t)HN_  * IN_];
__device__ __nv_bfloat16 g_w1l[(size_t)HN_  * IN_];
__device__ __nv_bfloat16 g_w2h[(size_t)OUT_ * KMIX];
__device__ __nv_bfloat16 g_w2l[(size_t)OUT_ * KMIX];
__device__ __nv_bfloat16 g_srh[(size_t)NTOK * KMIX];
__device__ __nv_bfloat16 g_srl[(size_t)NTOK * KMIX];

// ---------------------------------------------------------------- utils
__device__ __forceinline__ uint32_t smem_u32_of(const void* p) {
    uint32_t a;
    asm("{ .reg .u64 t; cvta.to.shared.u64 t, %1; cvt.u32.u64 %0, t; }"
        : "=r"(a) : "l"(p));
    return a;
}

#define LDSM4(r0, r1, r2, r3, addr)                                         \
    asm volatile("ldmatrix.sync.aligned.m8n8.x4.shared.b16 {%0,%1,%2,%3}, [%4];" \
        : "=r"(r0), "=r"(r1), "=r"(r2), "=r"(r3) : "r"(addr))

#define MMA_BF16(c, a, b)                                                   \
    asm volatile("mma.sync.aligned.m16n8k16.row.col.f32.bf16.bf16.f32 "     \
        "{%0,%1,%2,%3}, {%4,%5,%6,%7}, {%8,%9}, {%0,%1,%2,%3};"             \
        : "+f"((c)[0]), "+f"((c)[1]), "+f"((c)[2]), "+f"((c)[3])            \
        : "r"((a)[0]), "r"((a)[1]), "r"((a)[2]), "r"((a)[3]),               \
          "r"((b)[0]), "r"((b)[1]))

#define CP_ASYNC16(sp, gp)                                                  \
    asm volatile("cp.async.cg.shared.global [%0], [%1], 16;"                \
        :: "r"(sp), "l"(gp))
#define CP_COMMIT()   asm volatile("cp.async.commit_group;" ::: "memory")
#define CP_WAIT_1()   asm volatile("cp.async.wait_group 1;" ::: "memory")
#define CP_WAIT_0()   asm volatile("cp.async.wait_group 0;" ::: "memory")

// ---------------------------------------------------------------- split
__global__ void split_kernel(const float* __restrict__ src,
                             __nv_bfloat16* __restrict__ hi,
                             __nv_bfloat16* __restrict__ lo, int n4)
{
    int i = blockIdx.x * blockDim.x + threadIdx.x;
    if (i >= n4) return;
    float4 v = ((const float4*)src)[i];
    __nv_bfloat16 h0 = __float2bfloat16_rn(v.x);
    __nv_bfloat16 h1 = __float2bfloat16_rn(v.y);
    __nv_bfloat16 h2 = __float2bfloat16_rn(v.z);
    __nv_bfloat16 h3 = __float2bfloat16_rn(v.w);
    __nv_bfloat16 l0 = __float2bfloat16_rn(v.x - __bfloat162float(h0));
    __nv_bfloat16 l1 = __float2bfloat16_rn(v.y - __bfloat162float(h1));
    __nv_bfloat16 l2 = __float2bfloat16_rn(v.z - __bfloat162float(h2));
    __nv_bfloat16 l3 = __float2bfloat16_rn(v.w - __bfloat162float(h3));
    ((__nv_bfloat162*)hi)[i*2+0] = __halves2bfloat162(h0, h1);
    ((__nv_bfloat162*)hi)[i*2+1] = __halves2bfloat162(h2, h3);
    ((__nv_bfloat162*)lo)[i*2+0] = __halves2bfloat162(l0, l1);
    ((__nv_bfloat162*)lo)[i*2+1] = __halves2bfloat162(l2, l3);
}

// ---------------------------------------------------------------- MMA GEMM
// C[M,N] = Ah@Bh^T + Ah@Bl^T + Al@Bh^T + bias (fp32 accum, mma.sync bf16)
// CTA tile 128x128, 512 threads / 16 warps (warp tile 32x32 => 4 warps/SMSP),
// K-chunk 64, 3-stage cp.async pipeline, one __syncthreads per chunk.
#define PADW    72
#define TB      (128 * PADW * 2)           // bytes per tensor tile: 18432
#define STG_B   (4 * TB)                   // bytes per stage: 73728
#define NST     3
#define SMEM_MMA (NST * STG_B)             // 221184
#define NTHR    512

__device__ __forceinline__ void ld_tile_async(uint32_t sdst,
                                              const __nv_bfloat16* __restrict__ g,
                                              int row0, int K, int k0, int tid)
{
#pragma unroll
    for (int it = 0; it < 2; ++it) {
        int idx = tid + (it << 9);          // 0..1023 16B vectors
        int row = idx >> 3, c8 = idx & 7;
        const void* gp = g + (size_t)(row0 + row) * K + k0 + c8 * 8;
        uint32_t sp = sdst + row * 144 + c8 * 16;
        CP_ASYNC16(sp, gp);
    }
}

__device__ __forceinline__ void ld_chunk(uint32_t sbase,
                                         const __nv_bfloat16* Ah, const __nv_bfloat16* Al,
                                         const __nv_bfloat16* Bh, const __nv_bfloat16* Bl,
                                         int bm, int bn, int K, int k0, int tid)
{
    ld_tile_async(sbase,          Ah, bm, K, k0, tid);
    ld_tile_async(sbase + TB,     Al, bm, K, k0, tid);
    ld_tile_async(sbase + 2 * TB, Bh, bn, K, k0, tid);
    ld_tile_async(sbase + 3 * TB, Bl, bn, K, k0, tid);
    CP_COMMIT();
}

__global__ __launch_bounds__(NTHR, 1)
void gemm_mma(const __nv_bfloat16* __restrict__ Ah, const __nv_bfloat16* __restrict__ Al,
              const __nv_bfloat16* __restrict__ Bh, const __nv_bfloat16* __restrict__ Bl,
              const float* __restrict__ bias, float* __restrict__ Cout,
              int K, int N)
{
    extern __shared__ char smem[];
    const uint32_t smb = smem_u32_of(smem);
    const int tid  = threadIdx.x;
    const int wid  = tid >> 5;
    const int lane = tid & 31;
    const int bm   = blockIdx.y << 7;
    const int bn   = blockIdx.x << 7;
    const int m0   = (wid & 3) * 32;        // warp M offset in tile (4 slots)
    const int n0   = (wid >> 2) * 32;       // warp N offset in tile (4 slots)

    float acc[2][4][4];
#pragma unroll
    for (int i = 0; i < 2; ++i)
#pragma unroll
        for (int j = 0; j < 4; ++j)
#pragma unroll
            for (int k = 0; k < 4; ++k) acc[i][j][k] = 0.f;

    const int nk = K >> 6;

    // prologue: chunks 0 and 1 into stages 0 and 1
    ld_chunk(smb,         Ah, Al, Bh, Bl, bm, bn, K, 0,  tid);
    ld_chunk(smb + STG_B, Ah, Al, Bh, Bl, bm, bn, K, 64, tid);

    // per-lane ldmatrix address components
    const int arow  = (lane & 7) + ((lane >> 3) & 1) * 8;   // A: row within 16
    const int akoff = (lane >> 4) * 8;                      // A: k offset
    const int bgrp  = lane >> 3;
    const int brow  = (lane & 7) + (bgrp >> 1) * 8;         // B: n within 16
    const int bkoff = (bgrp & 1) * 8;                       // B: k offset

    int stage = 0;                          // = i % NST
    for (int i = 0; i < nk; ++i) {
        if (i + 1 < nk) CP_WAIT_1(); else CP_WAIT_0();
        __syncthreads();     // publishes chunk i; retires reads of stage being reloaded

        if (i + 2 < nk) {
            int st = stage + 2; if (st >= NST) st -= NST;
            ld_chunk(smb + st * STG_B, Ah, Al, Bh, Bl, bm, bn, K, (i + 2) << 6, tid);
        }

        const uint32_t sA  = smb + stage * STG_B;
        const uint32_t sAh = sA;
        const uint32_t sAl = sA + TB;
        const uint32_t sBh = sA + 2 * TB;
        const uint32_t sBl = sA + 3 * TB;

#pragma unroll
        for (int kk = 0; kk < 4; ++kk) {
            uint32_t ah[2][4], al[2][4], bh[4][2], bl[4][2];
#pragma unroll
            for (int mt = 0; mt < 2; ++mt) {
                uint32_t aoff = (uint32_t)(m0 + mt * 16 + arow) * 144
                              + (uint32_t)(kk * 16 + akoff) * 2;
                LDSM4(ah[mt][0], ah[mt][1], ah[mt][2], ah[mt][3], sAh + aoff);
                LDSM4(al[mt][0], al[mt][1], al[mt][2], al[mt][3], sAl + aoff);
            }
#pragma unroll
            for (int hf = 0; hf < 2; ++hf) {
                uint32_t boff = (uint32_t)(n0 + hf * 16 + brow) * 144
                              + (uint32_t)(kk * 16 + bkoff) * 2;
                uint32_t t0, t1, t2, t3;
                LDSM4(t0, t1, t2, t3, sBh + boff);
                bh[hf*2][0] = t0; bh[hf*2][1] = t1;
                bh[hf*2+1][0] = t2; bh[hf*2+1][1] = t3;
                LDSM4(t0, t1, t2, t3, sBl + boff);
                bl[hf*2][0] = t0; bl[hf*2][1] = t1;
                bl[hf*2+1][0] = t2; bl[hf*2+1][1] = t3;
            }
#pragma unroll
            for (int mt = 0; mt < 2; ++mt)
#pragma unroll
                for (int nt = 0; nt < 4; ++nt)
                    MMA_BF16(acc[mt][nt], ah[mt], bh[nt]);
#pragma unroll
            for (int mt = 0; mt < 2; ++mt)
#pragma unroll
                for (int nt = 0; nt < 4; ++nt)
                    MMA_BF16(acc[mt][nt], ah[mt], bl[nt]);
#pragma unroll
            for (int mt = 0; mt < 2; ++mt)
#pragma unroll
                for (int nt = 0; nt < 4; ++nt)
                    MMA_BF16(acc[mt][nt], al[mt], bh[nt]);
        }
        if (++stage >= NST) stage = 0;
    }

    // epilogue (+bias)
#pragma unroll
    for (int mt = 0; mt < 2; ++mt) {
#pragma unroll
        for (int nt = 0; nt < 4; ++nt) {
            int row = bm + m0 + mt * 16 + (lane >> 2);
            int col = bn + n0 + nt * 8 + 2 * (lane & 3);
            float b0 = bias[col], b1 = bias[col + 1];
            float2 v0 = make_float2(acc[mt][nt][0] + b0, acc[mt][nt][1] + b1);
            float2 v1 = make_float2(acc[mt][nt][2] + b0, acc[mt][nt][3] + b1);
            *(float2*)(Cout + (size_t)row * N + col)       = v0;
            *(float2*)(Cout + (size_t)(row + 8) * N + col) = v1;
        }
    }
}

// ---------------------------------------------------------------- gating
__global__ void gating_kernel()
{
    int g = blockIdx.x * blockDim.x + threadIdx.x;
    int t = g >> 6;
    int m = g & 63;
    const float* hr = g_h + (size_t)t * HN_;
    float hy = hr[m];
    float hg = hr[MEM_ + OUT_ + m];
    g_y[g] = hy * (1.f / (1.f + expf(-hg)));
}

// ---------------------------------------------------------------- scan
__global__ void scan_kernel(const float* __restrict__ a,
                            const float* __restrict__ bfreq,
                            float2* __restrict__ st,
                            float*  __restrict__ st_real)
{
    int g = blockIdx.x * blockDim.x + threadIdx.x;    // 0..B*MEM*C-1
    int c = g & (C_ - 1);
    int m = (g >> 5) & (MEM_ - 1);
    int b = g >> 11;

    float r   = expf(-fabsf(a[m]));
    float ang = bfreq[c];
    float gr  = r * cosf(ang);
    float gi  = r * sinf(ang);

    const float* yb = g_y + (size_t)b * T_ * MEM_ + m;
    const size_t base = ((size_t)b * T_ * MEM_ + m) * C_ + c;   // complex units
    float2* sb = st ? st + base : 0;
    float*  rb = st_real ? st_real + base : 0;
    __nv_bfloat162* sh = (__nv_bfloat162*)g_srh + base;
    __nv_bfloat162* sl = (__nv_bfloat162*)g_srl + base;

    float sr = 0.f, si = 0.f;
    for (int t = 0; t < T_; ++t) {
        float yv = yb[(size_t)t * MEM_];
        float nr = fmaf(gr, sr, fmaf(-gi, si, yv));
        float ni = fmaf(gr, si, gi * sr);
        sr = nr; si = ni;
        const size_t o = (size_t)t * (MEM_ * C_);
        if (sb) sb[o] = make_float2(sr, si);
        if (rb) rb[o] = sr;
        __nv_bfloat16 hr_ = __float2bfloat16_rn(sr);
        __nv_bfloat16 hi_ = __float2bfloat16_rn(si);
        __nv_bfloat16 lr_ = __float2bfloat16_rn(sr - __bfloat162float(hr_));
        __nv_bfloat16 li_ = __float2bfloat16_rn(si - __bfloat162float(hi_));
        sh[o] = __halves2bfloat162(hr_, hi_);
        sl[o] = __halves2bfloat162(lr_, li_);
    }
}

// ---------------------------------------------------------------- LN epi
__global__ __launch_bounds__(256)
void ln_epilogue(float* __restrict__ out)
{
    __shared__ float red[256];
    const int row = blockIdx.x;
    const int tid = threadIdx.x;
    const float* zr = g_z + (size_t)row * OUT_;

    float v[4];
    float s = 0.f;
#pragma unroll
    for (int j = 0; j < 4; ++j) { v[j] = zr[tid + (j << 8)]; s += v[j]; }
    red[tid] = s; __syncthreads();
    for (int off = 128; off > 0; off >>= 1) {
        if (tid < off) red[tid] += red[tid + off];
        __syncthreads();
    }
    float mu = red[0] * (1.f / OUT_);
    __syncthreads();
    float ss = 0.f;
#pragma unroll
    for (int j = 0; j < 4; ++j) { float d = v[j] - mu; ss += d * d; }
    red[tid] = ss; __syncthreads();
    for (int off = 128; off > 0; off >>= 1) {
        if (tid < off) red[tid] += red[tid + off];
        __syncthreads();
    }
    float inv = rsqrtf(red[0] * (1.f / OUT_) + 1e-5f);

    const float* hr = g_h + (size_t)row * HN_;
#pragma unroll
    for (int j = 0; j < 4; ++j) {
        int o = tid + (j << 8);
        float og   = 1.f / (1.f + expf(-hr[MEM_ + OUT_ + MEM_ + o]));
        float thru = hr[MEM_ + o];
        out[(size_t)row * OUT_ + o] = (v[j] - mu) * inv * og + thru * (1.f - og);
    }
}

// ---------------------------------------------------------------- launch
extern "C" void kernel_launch(void* const* d_in, const int* in_sizes, int n_in,
                              void* d_out, int out_size)
{
    (void)in_sizes; (void)n_in;
    const float* x     = (const float*)d_in[0];
    const float* pre_w = (const float*)d_in[1];
    const float* pre_b = (const float*)d_in[2];
    const float* a     = (const float*)d_in[3];
    const float* bfr   = (const float*)d_in[4];
    const float* mix_w = (const float*)d_in[5];
    const float* mix_b = (const float*)d_in[6];
    float* out = (float*)d_out;

    cudaFuncSetAttribute(gemm_mma, cudaFuncAttributeMaxDynamicSharedMemorySize,
                         SMEM_MMA);

    float *hbuf, *zbuf;
    __nv_bfloat16 *xh, *xl, *w1h, *w1l, *w2h, *w2l, *srh, *srl;
    cudaGetSymbolAddress((void**)&hbuf, g_h);
    cudaGetSymbolAddress((void**)&zbuf, g_z);
    cudaGetSymbolAddress((void**)&xh,  g_xh);  cudaGetSymbolAddress((void**)&xl,  g_xl);
    cudaGetSymbolAddress((void**)&w1h, g_w1h); cudaGetSymbolAddress((void**)&w1l, g_w1l);
    cudaGetSymbolAddress((void**)&w2h, g_w2h); cudaGetSymbolAddress((void**)&w2l, g_w2l);
    cudaGetSymbolAddress((void**)&srh, g_srh); cudaGetSymbolAddress((void**)&srl, g_srl);

    const long long OUT_ELEMS = (long long)NTOK * OUT_;        // 16,777,216
    const long long ST_CPLX_F = 2LL * NTOK * MEM_ * C_;        // 67,108,864
    const long long ST_REAL_F = (long long)NTOK * MEM_ * C_;   // 33,554,432
    const long long avail = (long long)out_size - OUT_ELEMS;

    float2* st_i = 0;
    float*  st_r = 0;
    if (avail >= ST_CPLX_F)       st_i = (float2*)(out + OUT_ELEMS);
    else if (avail >= ST_REAL_F)  st_r = out + OUT_ELEMS;

    // input splits (fp32 -> bf16 hi/lo)
    split_kernel<<<(NTOK*IN_/4 + 255)/256, 256>>>(x, xh, xl, NTOK*IN_/4);
    split_kernel<<<(HN_*IN_/4 + 255)/256, 256>>>(pre_w, w1h, w1l, HN_*IN_/4);
    split_kernel<<<(OUT_*KMIX/4 + 255)/256, 256>>>(mix_w, w2h, w2l, OUT_*KMIX/4);

    // 1) h = x @ pre_w^T + pre_b   (M=16384, N=2176, K=1024)
    gemm_mma<<<dim3(HN_/128, NTOK/128), NTHR, SMEM_MMA>>>(
        xh, xl, w1h, w1l, pre_b, hbuf, IN_, HN_);
    // 2) gated scan input
    gating_kernel<<<(NTOK * MEM_) / 256, 256>>>();
    // 3) scan -> states output + bf16 hi/lo sr
    scan_kernel<<<(B_ * MEM_ * C_) / 256, 256>>>(a, bfr, st_i, st_r);
    // 4) z = sr @ mix_w^T + mix_b  (M=16384, N=1024, K=4096)
    gemm_mma<<<dim3(OUT_/128, NTOK/128), NTHR, SMEM_MMA>>>(
        srh, srl, w2h, w2l, mix_b, zbuf, KMIX, OUT_);
    // 5) LN + gated mix
    ln_epilogue<<<NTOK, 256>>>(out);
}

// round 9
// speedup vs baseline: 1.3046x; 1.3046x over previous
#include <cuda_runtime.h>
#include <cuda_fp16.h>
#include <math.h>
#include <stdint.h>

// ---------------------------------------------------------------- constants
#define B_    16
#define T_    1024
#define IN_   1024
#define MEM_  64
#define OUT_  1024
#define C_    32
#define HN_   (2*MEM_ + 2*OUT_)      // 2176
#define NTOK  (B_*T_)                // 16384
#define KMIX  (MEM_*2*C_)            // 4096

// ---------------------------------------------------------------- scratch
__device__ float g_h [(size_t)NTOK * HN_];
__device__ float g_y [(size_t)NTOK * MEM_];
__device__ float g_z [(size_t)NTOK * OUT_];
__device__ __half g_xh [(size_t)NTOK * IN_];
__device__ __half g_xl [(size_t)NTOK * IN_];
__device__ __half g_w1h[(size_t)HN_  * IN_];
__device__ __half g_w2h[(size_t)OUT_ * KMIX];
__device__ __half g_srh[(size_t)NTOK * KMIX];
__device__ __half g_srl[(size_t)NTOK * KMIX];

// ---------------------------------------------------------------- utils
__device__ __forceinline__ uint32_t smem_u32_of(const void* p) {
    uint32_t a;
    asm("{ .reg .u64 t; cvta.to.shared.u64 t, %1; cvt.u32.u64 %0, t; }"
        : "=r"(a) : "l"(p));
    return a;
}

#define LDSM4(r0, r1, r2, r3, addr)                                         \
    asm volatile("ldmatrix.sync.aligned.m8n8.x4.shared.b16 {%0,%1,%2,%3}, [%4];" \
        : "=r"(r0), "=r"(r1), "=r"(r2), "=r"(r3) : "r"(addr))

#define MMA_F16(c, a, b)                                                    \
    asm volatile("mma.sync.aligned.m16n8k16.row.col.f32.f16.f16.f32 "       \
        "{%0,%1,%2,%3}, {%4,%5,%6,%7}, {%8,%9}, {%0,%1,%2,%3};"             \
        : "+f"((c)[0]), "+f"((c)[1]), "+f"((c)[2]), "+f"((c)[3])            \
        : "r"((a)[0]), "r"((a)[1]), "r"((a)[2]), "r"((a)[3]),               \
          "r"((b)[0]), "r"((b)[1]))

#define CP_ASYNC16(sp, gp)                                                  \
    asm volatile("cp.async.cg.shared.global [%0], [%1], 16;"                \
        :: "r"(sp), "l"(gp))
#define CP_COMMIT()   asm volatile("cp.async.commit_group;" ::: "memory")
#define CP_WAIT_1()   asm volatile("cp.async.wait_group 1;" ::: "memory")
#define CP_WAIT_0()   asm volatile("cp.async.wait_group 0;" ::: "memory")

// ---------------------------------------------------------------- splits
// hi/lo fp16 split (A operands: exact to ~2^-22)
__global__ void split2_kernel(const float* __restrict__ src,
                              __half* __restrict__ hi,
                              __half* __restrict__ lo, int n4)
{
    int i = blockIdx.x * blockDim.x + threadIdx.x;
    if (i >= n4) return;
    float4 v = ((const float4*)src)[i];
    __half h0 = __float2half_rn(v.x);
    __half h1 = __float2half_rn(v.y);
    __half h2 = __float2half_rn(v.z);
    __half h3 = __float2half_rn(v.w);
    __half l0 = __float2half_rn(v.x - __half2float(h0));
    __half l1 = __float2half_rn(v.y - __half2float(h1));
    __half l2 = __float2half_rn(v.z - __half2float(h2));
    __half l3 = __float2half_rn(v.w - __half2float(h3));
    ((__half2*)hi)[i*2+0] = __halves2half2(h0, h1);
    ((__half2*)hi)[i*2+1] = __halves2half2(h2, h3);
    ((__half2*)lo)[i*2+0] = __halves2half2(l0, l1);
    ((__half2*)lo)[i*2+1] = __halves2half2(l2, l3);
}

// hi-only fp16 round (B operands / weights)
__global__ void splitw_kernel(const float* __restrict__ src,
                              __half* __restrict__ hi, int n4)
{
    int i = blockIdx.x * blockDim.x + threadIdx.x;
    if (i >= n4) return;
    float4 v = ((const float4*)src)[i];
    ((__half2*)hi)[i*2+0] = __halves2half2(__float2half_rn(v.x), __float2half_rn(v.y));
    ((__half2*)hi)[i*2+1] = __halves2half2(__float2half_rn(v.z), __float2half_rn(v.w));
}

// ---------------------------------------------------------------- MMA GEMM
// C[M,N] = (Ah + Al) @ Bh^T + bias  (fp32 accum, mma.sync fp16, 2 terms)
// CTA tile 128x128, 256 threads / 8 warps (warp tile 64x32), K-chunk 64,
// 3-stage cp.async pipeline, one __syncthreads per chunk.
#define PADW    72
#define TB      (128 * PADW * 2)           // bytes per tile: 18432
#define STG_B   (3 * TB)                   // bytes per stage: 55296
#define NST     3
#define SMEM_MMA (NST * STG_B)             // 165888

__device__ __forceinline__ void ld_tile_async(uint32_t sdst,
                                              const __half* __restrict__ g,
                                              int row0, int K, int k0, int tid)
{
#pragma unroll
    for (int it = 0; it < 4; ++it) {
        int idx = tid + (it << 8);          // 0..1023 16B vectors
        int row = idx >> 3, c8 = idx & 7;
        const void* gp = g + (size_t)(row0 + row) * K + k0 + c8 * 8;
        uint32_t sp = sdst + row * 144 + c8 * 16;
        CP_ASYNC16(sp, gp);
    }
}

__device__ __forceinline__ void ld_chunk(uint32_t sbase,
                                         const __half* Ah, const __half* Al,
                                         const __half* Bh,
                                         int bm, int bn, int K, int k0, int tid)
{
    ld_tile_async(sbase,          Ah, bm, K, k0, tid);
    ld_tile_async(sbase + TB,     Al, bm, K, k0, tid);
    ld_tile_async(sbase + 2 * TB, Bh, bn, K, k0, tid);
    CP_COMMIT();
}

__global__ __launch_bounds__(256, 1)
void gemm_mma(const __half* __restrict__ Ah, const __half* __restrict__ Al,
              const __half* __restrict__ Bh,
              const float* __restrict__ bias, float* __restrict__ Cout,
              int K, int N)
{
    extern __shared__ char smem[];
    const uint32_t smb = smem_u32_of(smem);
    const int tid  = threadIdx.x;
    const int wid  = tid >> 5;
    const int lane = tid & 31;
    const int bm   = blockIdx.y << 7;
    const int bn   = blockIdx.x << 7;
    const int m0   = (wid & 1) * 64;        // warp M offset in tile
    const int n0   = (wid >> 1) * 32;       // warp N offset in tile

    float acc[4][4][4];
#pragma unroll
    for (int i = 0; i < 4; ++i)
#pragma unroll
        for (int j = 0; j < 4; ++j)
#pragma unroll
            for (int k = 0; k < 4; ++k) acc[i][j][k] = 0.f;

    const int nk = K >> 6;

    // prologue: chunks 0 and 1 into stages 0 and 1
    ld_chunk(smb,         Ah, Al, Bh, bm, bn, K, 0,  tid);
    ld_chunk(smb + STG_B, Ah, Al, Bh, bm, bn, K, 64, tid);

    // per-lane ldmatrix address components
    const int arow  = (lane & 7) + ((lane >> 3) & 1) * 8;   // A: row within 16
    const int akoff = (lane >> 4) * 8;                      // A: k offset
    const int bgrp  = lane >> 3;
    const int brow  = (lane & 7) + (bgrp >> 1) * 8;         // B: n within 16
    const int bkoff = (bgrp & 1) * 8;                       // B: k offset

    int stage = 0;                          // = i % NST
    for (int i = 0; i < nk; ++i) {
        if (i + 1 < nk) CP_WAIT_1(); else CP_WAIT_0();
        __syncthreads();     // publishes chunk i; retires reads of stage being reloaded

        if (i + 2 < nk) {
            int st = stage + 2; if (st >= NST) st -= NST;
            ld_chunk(smb + st * STG_B, Ah, Al, Bh, bm, bn, K, (i + 2) << 6, tid);
        }

        const uint32_t sA  = smb + stage * STG_B;
        const uint32_t sAh = sA;
        const uint32_t sAl = sA + TB;
        const uint32_t sBh = sA + 2 * TB;

#pragma unroll
        for (int kk = 0; kk < 4; ++kk) {
            uint32_t ah[4][4], al[4][4], bh[4][2];
#pragma unroll
            for (int mt = 0; mt < 4; ++mt) {
                uint32_t aoff = (uint32_t)(m0 + mt * 16 + arow) * 144
                              + (uint32_t)(kk * 16 + akoff) * 2;
                LDSM4(ah[mt][0], ah[mt][1], ah[mt][2], ah[mt][3], sAh + aoff);
                LDSM4(al[mt][0], al[mt][1], al[mt][2], al[mt][3], sAl + aoff);
            }
#pragma unroll
            for (int hf = 0; hf < 2; ++hf) {
                uint32_t boff = (uint32_t)(n0 + hf * 16 + brow) * 144
                              + (uint32_t)(kk * 16 + bkoff) * 2;
                uint32_t t0, t1, t2, t3;
                LDSM4(t0, t1, t2, t3, sBh + boff);
                bh[hf*2][0] = t0; bh[hf*2][1] = t1;
                bh[hf*2+1][0] = t2; bh[hf*2+1][1] = t3;
            }
#pragma unroll
            for (int mt = 0; mt < 4; ++mt)
#pragma unroll
                for (int nt = 0; nt < 4; ++nt)
                    MMA_F16(acc[mt][nt], ah[mt], bh[nt]);
#pragma unroll
            for (int mt = 0; mt < 4; ++mt)
#pragma unroll
                for (int nt = 0; nt < 4; ++nt)
                    MMA_F16(acc[mt][nt], al[mt], bh[nt]);
        }
        if (++stage >= NST) stage = 0;
    }

    // epilogue (+bias)
#pragma unroll
    for (int mt = 0; mt < 4; ++mt) {
#pragma unroll
        for (int nt = 0; nt < 4; ++nt) {
            int row = bm + m0 + mt * 16 + (lane >> 2);
            int col = bn + n0 + nt * 8 + 2 * (lane & 3);
            float b0 = bias[col], b1 = bias[col + 1];
            float2 v0 = make_float2(acc[mt][nt][0] + b0, acc[mt][nt][1] + b1);
            float2 v1 = make_float2(acc[mt][nt][2] + b0, acc[mt][nt][3] + b1);
            *(float2*)(Cout + (size_t)row * N + col)       = v0;
            *(float2*)(Cout + (size_t)(row + 8) * N + col) = v1;
        }
    }
}

// ---------------------------------------------------------------- gating
__global__ void gating_kernel()
{
    int g = blockIdx.x * blockDim.x + threadIdx.x;
    int t = g >> 6;
    int m = g & 63;
    const float* hr = g_h + (size_t)t * HN_;
    float hy = hr[m];
    float hg = hr[MEM_ + OUT_ + m];
    g_y[g] = hy * (1.f / (1.f + expf(-hg)));
}

// ---------------------------------------------------------------- scan
__global__ void scan_kernel(const float* __restrict__ a,
                            const float* __restrict__ bfreq,
                            float2* __restrict__ st,
                            float*  __restrict__ st_real)
{
    int g = blockIdx.x * blockDim.x + threadIdx.x;    // 0..B*MEM*C-1
    int c = g & (C_ - 1);
    int m = (g >> 5) & (MEM_ - 1);
    int b = g >> 11;

    float r   = expf(-fabsf(a[m]));
    float ang = bfreq[c];
    float gr  = r * cosf(ang);
    float gi  = r * sinf(ang);

    const float* yb = g_y + (size_t)b * T_ * MEM_ + m;
    const size_t base = ((size_t)b * T_ * MEM_ + m) * C_ + c;   // complex units
    float2* sb = st ? st + base : 0;
    float*  rb = st_real ? st_real + base : 0;
    __half2* sh = (__half2*)g_srh + base;
    __half2* sl = (__half2*)g_srl + base;

    float sr = 0.f, si = 0.f;
    for (int t = 0; t < T_; ++t) {
        float yv = yb[(size_t)t * MEM_];
        float nr = fmaf(gr, sr, fmaf(-gi, si, yv));
        float ni = fmaf(gr, si, gi * sr);
        sr = nr; si = ni;
        const size_t o = (size_t)t * (MEM_ * C_);
        if (sb) sb[o] = make_float2(sr, si);
        if (rb) rb[o] = sr;
        __half hr_ = __float2half_rn(sr);
        __half hi_ = __float2half_rn(si);
        __half lr_ = __float2half_rn(sr - __half2float(hr_));
        __half li_ = __float2half_rn(si - __half2float(hi_));
        sh[o] = __halves2half2(hr_, hi_);
        sl[o] = __halves2half2(lr_, li_);
    }
}

// ---------------------------------------------------------------- LN epi
__global__ __launch_bounds__(256)
void ln_epilogue(float* __restrict__ out)
{
    __shared__ float red[256];
    const int row = blockIdx.x;
    const int tid = threadIdx.x;
    const float* zr = g_z + (size_t)row * OUT_;

    float v[4];
    float s = 0.f;
#pragma unroll
    for (int j = 0; j < 4; ++j) { v[j] = zr[tid + (j << 8)]; s += v[j]; }
    red[tid] = s; __syncthreads();
    for (int off = 128; off > 0; off >>= 1) {
        if (tid < off) red[tid] += red[tid + off];
        __syncthreads();
    }
    float mu = red[0] * (1.f / OUT_);
    __syncthreads();
    float ss = 0.f;
#pragma unroll
    for (int j = 0; j < 4; ++j) { float d = v[j] - mu; ss += d * d; }
    red[tid] = ss; __syncthreads();
    for (int off = 128; off > 0; off >>= 1) {
        if (tid < off) red[tid] += red[tid + off];
        __syncthreads();
    }
    float inv = rsqrtf(red[0] * (1.f / OUT_) + 1e-5f);

    const float* hr = g_h + (size_t)row * HN_;
#pragma unroll
    for (int j = 0; j < 4; ++j) {
        int o = tid + (j << 8);
        float og   = 1.f / (1.f + expf(-hr[MEM_ + OUT_ + MEM_ + o]));
        float thru = hr[MEM_ + o];
        out[(size_t)row * OUT_ + o] = (v[j] - mu) * inv * og + thru * (1.f - og);
    }
}

// ---------------------------------------------------------------- launch
extern "C" void kernel_launch(void* const* d_in, const int* in_sizes, int n_in,
                              void* d_out, int out_size)
{
    (void)in_sizes; (void)n_in;
    const float* x     = (const float*)d_in[0];
    const float* pre_w = (const float*)d_in[1];
    const float* pre_b = (const float*)d_in[2];
    const float* a     = (const float*)d_in[3];
    const float* bfr   = (const float*)d_in[4];
    const float* mix_w = (const float*)d_in[5];
    const float* mix_b = (const float*)d_in[6];
    float* out = (float*)d_out;

    cudaFuncSetAttribute(gemm_mma, cudaFuncAttributeMaxDynamicSharedMemorySize,
                         SMEM_MMA);

    float *hbuf, *zbuf;
    __half *xh, *xl, *w1h, *w2h, *srh, *srl;
    cudaGetSymbolAddress((void**)&hbuf, g_h);
    cudaGetSymbolAddress((void**)&zbuf, g_z);
    cudaGetSymbolAddress((void**)&xh,  g_xh);  cudaGetSymbolAddress((void**)&xl,  g_xl);
    cudaGetSymbolAddress((void**)&w1h, g_w1h);
    cudaGetSymbolAddress((void**)&w2h, g_w2h);
    cudaGetSymbolAddress((void**)&srh, g_srh); cudaGetSymbolAddress((void**)&srl, g_srl);

    const long long OUT_ELEMS = (long long)NTOK * OUT_;        // 16,777,216
    const long long ST_CPLX_F = 2LL * NTOK * MEM_ * C_;        // 67,108,864
    const long long ST_REAL_F = (long long)NTOK * MEM_ * C_;   // 33,554,432
    const long long avail = (long long)out_size - OUT_ELEMS;

    float2* st_i = 0;
    float*  st_r = 0;
    if (avail >= ST_CPLX_F)       st_i = (float2*)(out + OUT_ELEMS);
    else if (avail >= ST_REAL_F)  st_r = out + OUT_ELEMS;

    // input splits
    split2_kernel<<<(NTOK*IN_/4 + 255)/256, 256>>>(x, xh, xl, NTOK*IN_/4);
    splitw_kernel<<<(HN_*IN_/4 + 255)/256, 256>>>(pre_w, w1h, HN_*IN_/4);
    splitw_kernel<<<(OUT_*KMIX/4 + 255)/256, 256>>>(mix_w, w2h, OUT_*KMIX/4);

    // 1) h = x @ pre_w^T + pre_b   (M=16384, N=2176, K=1024)
    gemm_mma<<<dim3(HN_/128, NTOK/128), 256, SMEM_MMA>>>(
        xh, xl, w1h, pre_b, hbuf, IN_, HN_);
    // 2) gated scan input
    gating_kernel<<<(NTOK * MEM_) / 256, 256>>>();
    // 3) scan -> states output + fp16 hi/lo sr
    scan_kernel<<<(B_ * MEM_ * C_) / 256, 256>>>(a, bfr, st_i, st_r);
    // 4) z = sr @ mix_w^T + mix_b  (M=16384, N=1024, K=4096)
    gemm_mma<<<dim3(OUT_/128, NTOK/128), 256, SMEM_MMA>>>(
        srh, srl, w2h, mix_b, zbuf, KMIX, OUT_);
    // 5) LN + gated mix
    ln_epilogue<<<NTOK, 256>>>(out);
}

// round 10
// speedup vs baseline: 2.0530x; 1.5738x over previous
#include <cuda_runtime.h>
#include <cuda_fp16.h>
#include <math.h>
#include <stdint.h>

// ---------------------------------------------------------------- constants
#define B_    16
#define T_    1024
#define IN_   1024
#define MEM_  64
#define OUT_  1024
#define C_    32
#define HN_   (2*MEM_ + 2*OUT_)      // 2176
#define NTOK  (B_*T_)                // 16384
#define KMIX  (MEM_*2*C_)            // 4096

// ---------------------------------------------------------------- scratch
__device__ float g_h [(size_t)NTOK * HN_];
__device__ float g_y [(size_t)NTOK * MEM_];
__device__ float g_z [(size_t)NTOK * OUT_];
__device__ __half g_xh [(size_t)NTOK * IN_];
__device__ __half g_w1h[(size_t)HN_  * IN_];
__device__ __half g_w2h[(size_t)OUT_ * KMIX];
__device__ __half g_srh[(size_t)NTOK * KMIX];

// ---------------------------------------------------------------- utils
__device__ __forceinline__ uint32_t smem_u32_of(const void* p) {
    uint32_t a;
    asm("{ .reg .u64 t; cvta.to.shared.u64 t, %1; cvt.u32.u64 %0, t; }"
        : "=r"(a) : "l"(p));
    return a;
}

#define LDSM4(r0, r1, r2, r3, addr)                                         \
    asm volatile("ldmatrix.sync.aligned.m8n8.x4.shared.b16 {%0,%1,%2,%3}, [%4];" \
        : "=r"(r0), "=r"(r1), "=r"(r2), "=r"(r3) : "r"(addr))

#define MMA_F16(c, a, b)                                                    \
    asm volatile("mma.sync.aligned.m16n8k16.row.col.f32.f16.f16.f32 "       \
        "{%0,%1,%2,%3}, {%4,%5,%6,%7}, {%8,%9}, {%0,%1,%2,%3};"             \
        : "+f"((c)[0]), "+f"((c)[1]), "+f"((c)[2]), "+f"((c)[3])            \
        : "r"((a)[0]), "r"((a)[1]), "r"((a)[2]), "r"((a)[3]),               \
          "r"((b)[0]), "r"((b)[1]))

#define CP_ASYNC16(sp, gp)                                                  \
    asm volatile("cp.async.cg.shared.global [%0], [%1], 16;"                \
        :: "r"(sp), "l"(gp))
#define CP_COMMIT()   asm volatile("cp.async.commit_group;" ::: "memory")
#define CP_WAIT_1()   asm volatile("cp.async.wait_group 1;" ::: "memory")
#define CP_WAIT_0()   asm volatile("cp.async.wait_group 0;" ::: "memory")

// ---------------------------------------------------------------- split
// fp32 -> fp16 round (both GEMM operands use hi-only now)
__global__ void splitw_kernel(const float* __restrict__ src,
                              __half* __restrict__ hi, int n4)
{
    int i = blockIdx.x * blockDim.x + threadIdx.x;
    if (i >= n4) return;
    float4 v = ((const float4*)src)[i];
    ((__half2*)hi)[i*2+0] = __halves2half2(__float2half_rn(v.x), __float2half_rn(v.y));
    ((__half2*)hi)[i*2+1] = __halves2half2(__float2half_rn(v.z), __float2half_rn(v.w));
}

// ---------------------------------------------------------------- MMA GEMM
// C[M,N] = Ah @ Bh^T + bias  (fp32 accum, fp16 mma.sync, single term)
// CTA tile 128x128, 256 threads / 8 warps (warp tile 64x32), K-chunk 64,
// 3-stage cp.async pipeline, 2 CTAs/SM.
#define PADW    72
#define TB      (128 * PADW * 2)           // bytes per tile: 18432
#define STG_B   (2 * TB)                   // bytes per stage: 36864
#define NST     3
#define SMEM_MMA (NST * STG_B)             // 110592

__device__ __forceinline__ void ld_tile_async(uint32_t sdst,
                                              const __half* __restrict__ g,
                                              int row0, int K, int k0, int tid)
{
#pragma unroll
    for (int it = 0; it < 4; ++it) {
        int idx = tid + (it << 8);          // 0..1023 16B vectors
        int row = idx >> 3, c8 = idx & 7;
        const void* gp = g + (size_t)(row0 + row) * K + k0 + c8 * 8;
        uint32_t sp = sdst + row * 144 + c8 * 16;
        CP_ASYNC16(sp, gp);
    }
}

__device__ __forceinline__ void ld_chunk(uint32_t sbase,
                                         const __half* Ah, const __half* Bh,
                                         int bm, int bn, int K, int k0, int tid)
{
    ld_tile_async(sbase,      Ah, bm, K, k0, tid);
    ld_tile_async(sbase + TB, Bh, bn, K, k0, tid);
    CP_COMMIT();
}

__global__ __launch_bounds__(256, 2)
void gemm_mma(const __half* __restrict__ Ah, const __half* __restrict__ Bh,
              const float* __restrict__ bias, float* __restrict__ Cout,
              int K, int N)
{
    extern __shared__ char smem[];
    const uint32_t smb = smem_u32_of(smem);
    const int tid  = threadIdx.x;
    const int wid  = tid >> 5;
    const int lane = tid & 31;
    const int bm   = blockIdx.y << 7;
    const int bn   = blockIdx.x << 7;
    const int m0   = (wid & 1) * 64;        // warp M offset in tile
    const int n0   = (wid >> 1) * 32;       // warp N offset in tile

    float acc[4][4][4];
#pragma unroll
    for (int i = 0; i < 4; ++i)
#pragma unroll
        for (int j = 0; j < 4; ++j)
#pragma unroll
            for (int k = 0; k < 4; ++k) acc[i][j][k] = 0.f;

    const int nk = K >> 6;

    // prologue: chunks 0 and 1 into stages 0 and 1
    ld_chunk(smb,         Ah, Bh, bm, bn, K, 0,  tid);
    ld_chunk(smb + STG_B, Ah, Bh, bm, bn, K, 64, tid);

    // per-lane ldmatrix address components
    const int arow  = (lane & 7) + ((lane >> 3) & 1) * 8;   // A: row within 16
    const int akoff = (lane >> 4) * 8;                      // A: k offset
    const int bgrp  = lane >> 3;
    const int brow  = (lane & 7) + (bgrp >> 1) * 8;         // B: n within 16
    const int bkoff = (bgrp & 1) * 8;                       // B: k offset

    int stage = 0;                          // = i % NST
    for (int i = 0; i < nk; ++i) {
        if (i + 1 < nk) CP_WAIT_1(); else CP_WAIT_0();
        __syncthreads();     // publishes chunk i; retires reads of stage being reloaded

        if (i + 2 < nk) {
            int st = stage + 2; if (st >= NST) st -= NST;
            ld_chunk(smb + st * STG_B, Ah, Bh, bm, bn, K, (i + 2) << 6, tid);
        }

        const uint32_t sAh = smb + stage * STG_B;
        const uint32_t sBh = sAh + TB;

#pragma unroll
        for (int kk = 0; kk < 4; ++kk) {
            uint32_t ah[4][4], bh[4][2];
#pragma unroll
            for (int mt = 0; mt < 4; ++mt) {
                uint32_t aoff = (uint32_t)(m0 + mt * 16 + arow) * 144
                              + (uint32_t)(kk * 16 + akoff) * 2;
                LDSM4(ah[mt][0], ah[mt][1], ah[mt][2], ah[mt][3], sAh + aoff);
            }
#pragma unroll
            for (int hf = 0; hf < 2; ++hf) {
                uint32_t boff = (uint32_t)(n0 + hf * 16 + brow) * 144
                              + (uint32_t)(kk * 16 + bkoff) * 2;
                uint32_t t0, t1, t2, t3;
                LDSM4(t0, t1, t2, t3, sBh + boff);
                bh[hf*2][0] = t0; bh[hf*2][1] = t1;
                bh[hf*2+1][0] = t2; bh[hf*2+1][1] = t3;
            }
#pragma unroll
            for (int mt = 0; mt < 4; ++mt)
#pragma unroll
                for (int nt = 0; nt < 4; ++nt)
                    MMA_F16(acc[mt][nt], ah[mt], bh[nt]);
        }
        if (++stage >= NST) stage = 0;
    }

    // epilogue (+bias)
#pragma unroll
    for (int mt = 0; mt < 4; ++mt) {
#pragma unroll
        for (int nt = 0; nt < 4; ++nt) {
            int row = bm + m0 + mt * 16 + (lane >> 2);
            int col = bn + n0 + nt * 8 + 2 * (lane & 3);
            float b0 = bias[col], b1 = bias[col + 1];
            float2 v0 = make_float2(acc[mt][nt][0] + b0, acc[mt][nt][1] + b1);
            float2 v1 = make_float2(acc[mt][nt][2] + b0, acc[mt][nt][3] + b1);
            *(float2*)(Cout + (size_t)row * N + col)       = v0;
            *(float2*)(Cout + (size_t)(row + 8) * N + col) = v1;
        }
    }
}

// ---------------------------------------------------------------- gating
__global__ void gating_kernel()
{
    int g = blockIdx.x * blockDim.x + threadIdx.x;
    int t = g >> 6;
    int m = g & 63;
    const float* hr = g_h + (size_t)t * HN_;
    float hy = hr[m];
    float hg = hr[MEM_ + OUT_ + m];
    g_y[g] = hy * (1.f / (1.f + expf(-hg)));
}

// ---------------------------------------------------------------- scan
__global__ void scan_kernel(const float* __restrict__ a,
                            const float* __restrict__ bfreq,
                            float2* __restrict__ st,
                            float*  __restrict__ st_real)
{
    int g = blockIdx.x * blockDim.x + threadIdx.x;    // 0..B*MEM*C-1
    int c = g & (C_ - 1);
    int m = (g >> 5) & (MEM_ - 1);
    int b = g >> 11;

    float r   = expf(-fabsf(a[m]));
    float ang = bfreq[c];
    float gr  = r * cosf(ang);
    float gi  = r * sinf(ang);

    const float* yb = g_y + (size_t)b * T_ * MEM_ + m;
    const size_t base = ((size_t)b * T_ * MEM_ + m) * C_ + c;   // complex units
    float2* sb = st ? st + base : 0;
    float*  rb = st_real ? st_real + base : 0;
    __half2* sh = (__half2*)g_srh + base;

    float sr = 0.f, si = 0.f;
    for (int t = 0; t < T_; ++t) {
        float yv = yb[(size_t)t * MEM_];
        float nr = fmaf(gr, sr, fmaf(-gi, si, yv));
        float ni = fmaf(gr, si, gi * sr);
        sr = nr; si = ni;
        const size_t o = (size_t)t * (MEM_ * C_);
        if (sb) sb[o] = make_float2(sr, si);
        if (rb) rb[o] = sr;
        sh[o] = __halves2half2(__float2half_rn(sr), __float2half_rn(si));
    }
}

// ---------------------------------------------------------------- LN epi
__global__ __launch_bounds__(256)
void ln_epilogue(float* __restrict__ out)
{
    __shared__ float red[256];
    const int row = blockIdx.x;
    const int tid = threadIdx.x;
    const float* zr = g_z + (size_t)row * OUT_;

    float v[4];
    float s = 0.f;
#pragma unroll
    for (int j = 0; j < 4; ++j) { v[j] = zr[tid + (j << 8)]; s += v[j]; }
    red[tid] = s; __syncthreads();
    for (int off = 128; off > 0; off >>= 1) {
        if (tid < off) red[tid] += red[tid + off];
        __syncthreads();
    }
    float mu = red[0] * (1.f / OUT_);
    __syncthreads();
    float ss = 0.f;
#pragma unroll
    for (int j = 0; j < 4; ++j) { float d = v[j] - mu; ss += d * d; }
    red[tid] = ss; __syncthreads();
    for (int off = 128; off > 0; off >>= 1) {
        if (tid < off) red[tid] += red[tid + off];
        __syncthreads();
    }
    float inv = rsqrtf(red[0] * (1.f / OUT_) + 1e-5f);

    const float* hr = g_h + (size_t)row * HN_;
#pragma unroll
    for (int j = 0; j < 4; ++j) {
        int o = tid + (j << 8);
        float og   = 1.f / (1.f + expf(-hr[MEM_ + OUT_ + MEM_ + o]));
        float thru = hr[MEM_ + o];
        out[(size_t)row * OUT_ + o] = (v[j] - mu) * inv * og + thru * (1.f - og);
    }
}

// ---------------------------------------------------------------- launch
extern "C" void kernel_launch(void* const* d_in, const int* in_sizes, int n_in,
                              void* d_out, int out_size)
{
    (void)in_sizes; (void)n_in;
    const float* x     = (const float*)d_in[0];
    const float* pre_w = (const float*)d_in[1];
    const float* pre_b = (const float*)d_in[2];
    const float* a     = (const float*)d_in[3];
    const float* bfr   = (const float*)d_in[4];
    const float* mix_w = (const float*)d_in[5];
    const float* mix_b = (const float*)d_in[6];
    float* out = (float*)d_out;

    cudaFuncSetAttribute(gemm_mma, cudaFuncAttributeMaxDynamicSharedMemorySize,
                         SMEM_MMA);

    float *hbuf, *zbuf;
    __half *xh, *w1h, *w2h, *srh;
    cudaGetSymbolAddress((void**)&hbuf, g_h);
    cudaGetSymbolAddress((void**)&zbuf, g_z);
    cudaGetSymbolAddress((void**)&xh,  g_xh);
    cudaGetSymbolAddress((void**)&w1h, g_w1h);
    cudaGetSymbolAddress((void**)&w2h, g_w2h);
    cudaGetSymbolAddress((void**)&srh, g_srh);

    const long long OUT_ELEMS = (long long)NTOK * OUT_;        // 16,777,216
    const long long ST_CPLX_F = 2LL * NTOK * MEM_ * C_;        // 67,108,864
    const long long ST_REAL_F = (long long)NTOK * MEM_ * C_;   // 33,554,432
    const long long avail = (long long)out_size - OUT_ELEMS;

    float2* st_i = 0;
    float*  st_r = 0;
    if (avail >= ST_CPLX_F)       st_i = (float2*)(out + OUT_ELEMS);
    else if (avail >= ST_REAL_F)  st_r = out + OUT_ELEMS;

    // fp32 -> fp16 rounds
    splitw_kernel<<<(NTOK*IN_/4 + 255)/256, 256>>>(x, xh, NTOK*IN_/4);
    splitw_kernel<<<(HN_*IN_/4 + 255)/256, 256>>>(pre_w, w1h, HN_*IN_/4);
    splitw_kernel<<<(OUT_*KMIX/4 + 255)/256, 256>>>(mix_w, w2h, OUT_*KMIX/4);

    // 1) h = x @ pre_w^T + pre_b   (M=16384, N=2176, K=1024)
    gemm_mma<<<dim3(HN_/128, NTOK/128), 256, SMEM_MMA>>>(
        xh, w1h, pre_b, hbuf, IN_, HN_);
    // 2) gated scan input
    gating_kernel<<<(NTOK * MEM_) / 256, 256>>>();
    // 3) scan -> states output + fp16 sr
    scan_kernel<<<(B_ * MEM_ * C_) / 256, 256>>>(a, bfr, st_i, st_r);
    // 4) z = sr @ mix_w^T + mix_b  (M=16384, N=1024, K=4096)
    gemm_mma<<<dim3(OUT_/128, NTOK/128), 256, SMEM_MMA>>>(
        srh, w2h, mix_b, zbuf, KMIX, OUT_);
    // 5) LN + gated mix
    ln_epilogue<<<NTOK, 256>>>(out);
}

// round 11
// speedup vs baseline: 2.9354x; 1.4298x over previous
#include <cuda_runtime.h>
#include <cuda_fp16.h>
#include <math.h>
#include <stdint.h>

// ---------------------------------------------------------------- constants
#define B_    16
#define T_    1024
#define IN_   1024
#define MEM_  64
#define OUT_  1024
#define C_    32
#define HN_   (2*MEM_ + 2*OUT_)      // 2176
#define NTOK  (B_*T_)                // 16384
#define KMIX  (MEM_*2*C_)            // 4096
#define NCH   8
#define CHLEN (T_/NCH)               // 128

// ---------------------------------------------------------------- scratch
__device__ float g_h [(size_t)NTOK * HN_];
__device__ float g_y [(size_t)NTOK * MEM_];
__device__ float g_z [(size_t)NTOK * OUT_];
__device__ float2 g_sum[(size_t)B_ * NCH * MEM_ * C_];   // chunk summaries (2MB)
__device__ __half g_xh [(size_t)NTOK * IN_];
__device__ __half g_w1h[(size_t)HN_  * IN_];
__device__ __half g_w2h[(size_t)OUT_ * KMIX];
__device__ __half g_srh[(size_t)NTOK * KMIX];

// ---------------------------------------------------------------- utils
__device__ __forceinline__ uint32_t smem_u32_of(const void* p) {
    uint32_t a;
    asm("{ .reg .u64 t; cvta.to.shared.u64 t, %1; cvt.u32.u64 %0, t; }"
        : "=r"(a) : "l"(p));
    return a;
}

#define LDSM4(r0, r1, r2, r3, addr)                                         \
    asm volatile("ldmatrix.sync.aligned.m8n8.x4.shared.b16 {%0,%1,%2,%3}, [%4];" \
        : "=r"(r0), "=r"(r1), "=r"(r2), "=r"(r3) : "r"(addr))

#define MMA_F16(c, a, b)                                                    \
    asm volatile("mma.sync.aligned.m16n8k16.row.col.f32.f16.f16.f32 "       \
        "{%0,%1,%2,%3}, {%4,%5,%6,%7}, {%8,%9}, {%0,%1,%2,%3};"             \
        : "+f"((c)[0]), "+f"((c)[1]), "+f"((c)[2]), "+f"((c)[3])            \
        : "r"((a)[0]), "r"((a)[1]), "r"((a)[2]), "r"((a)[3]),               \
          "r"((b)[0]), "r"((b)[1]))

#define CP_ASYNC16(sp, gp)                                                  \
    asm volatile("cp.async.cg.shared.global [%0], [%1], 16;"                \
        :: "r"(sp), "l"(gp))
#define CP_COMMIT()   asm volatile("cp.async.commit_group;" ::: "memory")
#define CP_WAIT_1()   asm volatile("cp.async.wait_group 1;" ::: "memory")
#define CP_WAIT_0()   asm volatile("cp.async.wait_group 0;" ::: "memory")

// ---------------------------------------------------------------- split
__global__ void splitw_kernel(const float* __restrict__ src,
                              __half* __restrict__ hi, int n4)
{
    int i = blockIdx.x * blockDim.x + threadIdx.x;
    if (i >= n4) return;
    float4 v = ((const float4*)src)[i];
    ((__half2*)hi)[i*2+0] = __halves2half2(__float2half_rn(v.x), __float2half_rn(v.y));
    ((__half2*)hi)[i*2+1] = __halves2half2(__float2half_rn(v.z), __float2half_rn(v.w));
}

// ---------------------------------------------------------------- MMA GEMM
// C[M,N] = Ah @ Bh^T + bias  (fp32 accum, fp16 mma.sync, single term)
#define PADW    72
#define TB      (128 * PADW * 2)           // bytes per tile: 18432
#define STG_B   (2 * TB)                   // bytes per stage: 36864
#define NST     3
#define SMEM_MMA (NST * STG_B)             // 110592

__device__ __forceinline__ void ld_tile_async(uint32_t sdst,
                                              const __half* __restrict__ g,
                                              int row0, int K, int k0, int tid)
{
#pragma unroll
    for (int it = 0; it < 4; ++it) {
        int idx = tid + (it << 8);          // 0..1023 16B vectors
        int row = idx >> 3, c8 = idx & 7;
        const void* gp = g + (size_t)(row0 + row) * K + k0 + c8 * 8;
        uint32_t sp = sdst + row * 144 + c8 * 16;
        CP_ASYNC16(sp, gp);
    }
}

__device__ __forceinline__ void ld_chunk(uint32_t sbase,
                                         const __half* Ah, const __half* Bh,
                                         int bm, int bn, int K, int k0, int tid)
{
    ld_tile_async(sbase,      Ah, bm, K, k0, tid);
    ld_tile_async(sbase + TB, Bh, bn, K, k0, tid);
    CP_COMMIT();
}

__global__ __launch_bounds__(256, 2)
void gemm_mma(const __half* __restrict__ Ah, const __half* __restrict__ Bh,
              const float* __restrict__ bias, float* __restrict__ Cout,
              int K, int N)
{
    extern __shared__ char smem[];
    const uint32_t smb = smem_u32_of(smem);
    const int tid  = threadIdx.x;
    const int wid  = tid >> 5;
    const int lane = tid & 31;
    const int bm   = blockIdx.y << 7;
    const int bn   = blockIdx.x << 7;
    const int m0   = (wid & 1) * 64;
    const int n0   = (wid >> 1) * 32;

    float acc[4][4][4];
#pragma unroll
    for (int i = 0; i < 4; ++i)
#pragma unroll
        for (int j = 0; j < 4; ++j)
#pragma unroll
            for (int k = 0; k < 4; ++k) acc[i][j][k] = 0.f;

    const int nk = K >> 6;

    ld_chunk(smb,         Ah, Bh, bm, bn, K, 0,  tid);
    ld_chunk(smb + STG_B, Ah, Bh, bm, bn, K, 64, tid);

    const int arow  = (lane & 7) + ((lane >> 3) & 1) * 8;
    const int akoff = (lane >> 4) * 8;
    const int bgrp  = lane >> 3;
    const int brow  = (lane & 7) + (bgrp >> 1) * 8;
    const int bkoff = (bgrp & 1) * 8;

    int stage = 0;
    for (int i = 0; i < nk; ++i) {
        if (i + 1 < nk) CP_WAIT_1(); else CP_WAIT_0();
        __syncthreads();

        if (i + 2 < nk) {
            int st = stage + 2; if (st >= NST) st -= NST;
            ld_chunk(smb + st * STG_B, Ah, Bh, bm, bn, K, (i + 2) << 6, tid);
        }

        const uint32_t sAh = smb + stage * STG_B;
        const uint32_t sBh = sAh + TB;

#pragma unroll
        for (int kk = 0; kk < 4; ++kk) {
            uint32_t ah[4][4], bh[4][2];
#pragma unroll
            for (int mt = 0; mt < 4; ++mt) {
                uint32_t aoff = (uint32_t)(m0 + mt * 16 + arow) * 144
                              + (uint32_t)(kk * 16 + akoff) * 2;
                LDSM4(ah[mt][0], ah[mt][1], ah[mt][2], ah[mt][3], sAh + aoff);
            }
#pragma unroll
            for (int hf = 0; hf < 2; ++hf) {
                uint32_t boff = (uint32_t)(n0 + hf * 16 + brow) * 144
                              + (uint32_t)(kk * 16 + bkoff) * 2;
                uint32_t t0, t1, t2, t3;
                LDSM4(t0, t1, t2, t3, sBh + boff);
                bh[hf*2][0] = t0; bh[hf*2][1] = t1;
                bh[hf*2+1][0] = t2; bh[hf*2+1][1] = t3;
            }
#pragma unroll
            for (int mt = 0; mt < 4; ++mt)
#pragma unroll
                for (int nt = 0; nt < 4; ++nt)
                    MMA_F16(acc[mt][nt], ah[mt], bh[nt]);
        }
        if (++stage >= NST) stage = 0;
    }

#pragma unroll
    for (int mt = 0; mt < 4; ++mt) {
#pragma unroll
        for (int nt = 0; nt < 4; ++nt) {
            int row = bm + m0 + mt * 16 + (lane >> 2);
            int col = bn + n0 + nt * 8 + 2 * (lane & 3);
            float b0 = bias[col], b1 = bias[col + 1];
            float2 v0 = make_float2(acc[mt][nt][0] + b0, acc[mt][nt][1] + b1);
            float2 v1 = make_float2(acc[mt][nt][2] + b0, acc[mt][nt][3] + b1);
            *(float2*)(Cout + (size_t)row * N + col)       = v0;
            *(float2*)(Cout + (size_t)(row + 8) * N + col) = v1;
        }
    }
}

// ---------------------------------------------------------------- gating
__global__ void gating_kernel()
{
    int g = blockIdx.x * blockDim.x + threadIdx.x;
    int t = g >> 6;
    int m = g & 63;
    const float* hr = g_h + (size_t)t * HN_;
    float hy = hr[m];
    float hg = hr[MEM_ + OUT_ + m];
    g_y[g] = hy * (1.f / (1.f + expf(-hg)));
}

// ---------------------------------------------------------------- scan
// s_t = gamma*s_{t-1} + y_t.  Two-phase chunked parallel scan over T.
// Thread index layout: g = ((b*NCH + ch)*MEM_ + m)*C_ + c.
__device__ __forceinline__ void scan_gamma(const float* a, const float* bfreq,
                                           int m, int c, float& gr, float& gi)
{
    float r   = expf(-fabsf(a[m]));
    float ang = bfreq[c];
    gr = r * cosf(ang);
    gi = r * sinf(ang);
}

__global__ void scan_phase1(const float* __restrict__ a,
                            const float* __restrict__ bfreq)
{
    int g = blockIdx.x * blockDim.x + threadIdx.x;   // B*NCH*MEM*C
    int c  = g & (C_ - 1);
    int m  = (g >> 5) & (MEM_ - 1);
    int ch = (g >> 11) & (NCH - 1);
    int b  = g >> 14;

    float gr, gi;
    scan_gamma(a, bfreq, m, c, gr, gi);

    const float* yb = g_y + ((size_t)b * T_ + ch * CHLEN) * MEM_ + m;
    float sr = 0.f, si = 0.f;
    for (int t = 0; t < CHLEN; ++t) {
        float yv = yb[(size_t)t * MEM_];
        float nr = fmaf(gr, sr, fmaf(-gi, si, yv));
        float ni = fmaf(gr, si, gi * sr);
        sr = nr; si = ni;
    }
    g_sum[g] = make_float2(sr, si);
}

__global__ void scan_phase2(const float* __restrict__ a,
                            const float* __restrict__ bfreq,
                            float2* __restrict__ st,
                            float*  __restrict__ st_real)
{
    int g = blockIdx.x * blockDim.x + threadIdx.x;
    int c  = g & (C_ - 1);
    int m  = (g >> 5) & (MEM_ - 1);
    int ch = (g >> 11) & (NCH - 1);
    int b  = g >> 14;

    float gr, gi;
    scan_gamma(a, bfreq, m, c, gr, gi);

    // gamma^CHLEN by 7 squarings (CHLEN = 128 = 2^7)
    float pr = gr, pi = gi;
#pragma unroll
    for (int s = 0; s < 7; ++s) {
        float nr = pr * pr - pi * pi;
        float ni = 2.f * pr * pi;
        pr = nr; pi = ni;
    }

    // carry = scan of previous chunk summaries
    float cr = 0.f, ci = 0.f;
    const size_t sum_stride = (size_t)MEM_ * C_;     // per-chunk stride in g_sum
    const size_t sum_base = ((size_t)b * NCH) * sum_stride + (size_t)m * C_ + c;
    for (int j = 0; j < ch; ++j) {
        float tr = cr * pr - ci * pi;
        float ti = cr * pi + ci * pr;
        float2 S = g_sum[sum_base + (size_t)j * sum_stride];
        cr = tr + S.x;
        ci = ti + S.y;
    }

    const int t0 = ch * CHLEN;
    const float* yb = g_y + ((size_t)b * T_ + t0) * MEM_ + m;
    const size_t base = (((size_t)b * T_ + t0) * MEM_ + m) * C_ + c;  // complex units
    float2* sb = st ? st + base : 0;
    float*  rb = st_real ? st_real + base : 0;
    __half2* sh = (__half2*)g_srh + base;

    float sr = cr, si = ci;
    for (int t = 0; t < CHLEN; ++t) {
        float yv = yb[(size_t)t * MEM_];
        float nr = fmaf(gr, sr, fmaf(-gi, si, yv));
        float ni = fmaf(gr, si, gi * sr);
        sr = nr; si = ni;
        const size_t o = (size_t)t * (MEM_ * C_);
        if (sb) sb[o] = make_float2(sr, si);
        if (rb) rb[o] = sr;
        sh[o] = __halves2half2(__float2half_rn(sr), __float2half_rn(si));
    }
}

// ---------------------------------------------------------------- LN epi
__global__ __launch_bounds__(256)
void ln_epilogue(float* __restrict__ out)
{
    __shared__ float red[256];
    const int row = blockIdx.x;
    const int tid = threadIdx.x;
    const float* zr = g_z + (size_t)row * OUT_;

    float v[4];
    float s = 0.f;
#pragma unroll
    for (int j = 0; j < 4; ++j) { v[j] = zr[tid + (j << 8)]; s += v[j]; }
    red[tid] = s; __syncthreads();
    for (int off = 128; off > 0; off >>= 1) {
        if (tid < off) red[tid] += red[tid + off];
        __syncthreads();
    }
    float mu = red[0] * (1.f / OUT_);
    __syncthreads();
    float ss = 0.f;
#pragma unroll
    for (int j = 0; j < 4; ++j) { float d = v[j] - mu; ss += d * d; }
    red[tid] = ss; __syncthreads();
    for (int off = 128; off > 0; off >>= 1) {
        if (tid < off) red[tid] += red[tid + off];
        __syncthreads();
    }
    float inv = rsqrtf(red[0] * (1.f / OUT_) + 1e-5f);

    const float* hr = g_h + (size_t)row * HN_;
#pragma unroll
    for (int j = 0; j < 4; ++j) {
        int o = tid + (j << 8);
        float og   = 1.f / (1.f + expf(-hr[MEM_ + OUT_ + MEM_ + o]));
        float thru = hr[MEM_ + o];
        out[(size_t)row * OUT_ + o] = (v[j] - mu) * inv * og + thru * (1.f - og);
    }
}

// ---------------------------------------------------------------- launch
extern "C" void kernel_launch(void* const* d_in, const int* in_sizes, int n_in,
                              void* d_out, int out_size)
{
    (void)in_sizes; (void)n_in;
    const float* x     = (const float*)d_in[0];
    const float* pre_w = (const float*)d_in[1];
    const float* pre_b = (const float*)d_in[2];
    const float* a     = (const float*)d_in[3];
    const float* bfr   = (const float*)d_in[4];
    const float* mix_w = (const float*)d_in[5];
    const float* mix_b = (const float*)d_in[6];
    float* out = (float*)d_out;

    cudaFuncSetAttribute(gemm_mma, cudaFuncAttributeMaxDynamicSharedMemorySize,
                         SMEM_MMA);

    float *hbuf, *zbuf;
    __half *xh, *w1h, *w2h, *srh;
    cudaGetSymbolAddress((void**)&hbuf, g_h);
    cudaGetSymbolAddress((void**)&zbuf, g_z);
    cudaGetSymbolAddress((void**)&xh,  g_xh);
    cudaGetSymbolAddress((void**)&w1h, g_w1h);
    cudaGetSymbolAddress((void**)&w2h, g_w2h);
    cudaGetSymbolAddress((void**)&srh, g_srh);

    const long long OUT_ELEMS = (long long)NTOK * OUT_;        // 16,777,216
    const long long ST_CPLX_F = 2LL * NTOK * MEM_ * C_;        // 67,108,864
    const long long ST_REAL_F = (long long)NTOK * MEM_ * C_;   // 33,554,432
    const long long avail = (long long)out_size - OUT_ELEMS;

    float2* st_i = 0;
    float*  st_r = 0;
    if (avail >= ST_CPLX_F)       st_i = (float2*)(out + OUT_ELEMS);
    else if (avail >= ST_REAL_F)  st_r = out + OUT_ELEMS;

    // fp32 -> fp16 rounds
    splitw_kernel<<<(NTOK*IN_/4 + 255)/256, 256>>>(x, xh, NTOK*IN_/4);
    splitw_kernel<<<(HN_*IN_/4 + 255)/256, 256>>>(pre_w, w1h, HN_*IN_/4);
    splitw_kernel<<<(OUT_*KMIX/4 + 255)/256, 256>>>(mix_w, w2h, OUT_*KMIX/4);

    // 1) h = x @ pre_w^T + pre_b   (M=16384, N=2176, K=1024)
    gemm_mma<<<dim3(HN_/128, NTOK/128), 256, SMEM_MMA>>>(
        xh, w1h, pre_b, hbuf, IN_, HN_);
    // 2) gated scan input
    gating_kernel<<<(NTOK * MEM_) / 256, 256>>>();
    // 3) two-phase parallel scan -> states output + fp16 sr
    const int nscan = B_ * NCH * MEM_ * C_;      // 262144
    scan_phase1<<<nscan / 256, 256>>>(a, bfr);
    scan_phase2<<<nscan / 256, 256>>>(a, bfr, st_i, st_r);
    // 4) z = sr @ mix_w^T + mix_b  (M=16384, N=1024, K=4096)
    gemm_mma<<<dim3(OUT_/128, NTOK/128), 256, SMEM_MMA>>>(
        srh, w2h, mix_b, zbuf, KMIX, OUT_);
    // 5) LN + gated mix
    ln_epilogue<<<NTOK, 256>>>(out);
}